// round 17
// baseline (speedup 1.0000x reference)
#include <cuda_runtime.h>
#include <cuda_fp16.h>
#include <cstdint>

#define NUM_B  2
#define SEQ    4096
#define CH     1280
#define CAdim  2048
#define NHEADS 20
#define HDIM   64
#define LTOT   101

// main fp16 GEMM tiling: 128x128 CTA tile, 4 warps, warp tile 64x64
#define BM 128
#define BN 128
#define BKH 32
#define GSTG 5
#define A_ST_BYTES (128*80)
#define B_ST_BYTES (32*272)
#define STAGE_BYTES (A_ST_BYTES + B_ST_BYTES)   // 18944
#define GEMM_SMEM (GSTG * STAGE_BYTES)          // 94720
#define KTILES (CH / BKH)       // 40

// kv fp16 GEMM tiling
#define KV_KC 64
#define KV_IT (CAdim / KV_KC)          // 32
#define KV_STG 6
#define KV_ROWB 144
#define KV_E_B (64 * KV_ROWB)
#define KV_W_B (64 * KV_ROWB)
#define KV_STAGE_B (KV_E_B + KV_W_B)   // 18432
#define KV_SMEM (KV_STG * KV_STAGE_B)  // 110592

// attention mma
#define AT_ROWB 144
#define AQ_OFF 0
#define AK_OFF (128*AT_ROWB)
#define AV_OFF (AK_OFF + 112*AT_ROWB)
#define AT_SMEM (AV_OFF + 112*AT_ROWB)   // 50688

__constant__ int c_seg_start[4] = {0, 77, 81, 85};
__constant__ int c_seg_len[4]   = {77, 4, 4, 16};
__constant__ int c_job_seg[12] = {0,0,0,1,2,3, 0,0,0,1,2,3};
__constant__ int c_job_m0[12]  = {0,64,128,0,0,0, 0,64,128,0,0,0};

__device__ uint16_t g_QH  [(size_t)NUM_B*SEQ*CH];
__device__ uint16_t g_KH  [(size_t)NUM_B*LTOT*CH];
__device__ uint16_t g_VH  [(size_t)NUM_B*LTOT*CH];
__device__ uint16_t g_hsH [(size_t)NUM_B*SEQ*CH];
__device__ uint16_t g_AttH[(size_t)NUM_B*SEQ*CH];
__device__ uint16_t g_WqH [(size_t)CH*CH];
__device__ uint16_t g_WoH [(size_t)CH*CH];
__device__ uint16_t g_WkvH[(size_t)8*CAdim*CH];
__device__ uint16_t g_ehsH[(size_t)NUM_B*LTOT*CAdim];

struct KVWeights { const float* w[8]; };

// Side stream + fork/join events, created at program load.
static cudaStream_t g_s2;
static cudaEvent_t  g_evFork, g_evJoin;
static struct StreamInit {
    StreamInit() {
        cudaStreamCreateWithFlags(&g_s2, cudaStreamNonBlocking);
        cudaEventCreateWithFlags(&g_evFork, cudaEventDisableTiming);
        cudaEventCreateWithFlags(&g_evJoin, cudaEventDisableTiming);
    }
} g_streamInit;

// ---------------------------------------------------------------------------
// helpers
// ---------------------------------------------------------------------------
__device__ __forceinline__ uint32_t smem_u32(const void* p) {
    uint32_t a;
    asm("{ .reg .u64 t; cvta.to.shared.u64 t, %1; cvt.u32.u64 %0, t; }"
        : "=r"(a) : "l"(p));
    return a;
}
__device__ __forceinline__ void cp_async16(void* smem_ptr, const void* gptr) {
    uint32_t sa = (uint32_t)__cvta_generic_to_shared(smem_ptr);
    asm volatile("cp.async.cg.shared.global [%0], [%1], 16;\n" :: "r"(sa), "l"(gptr));
}
__device__ __forceinline__ void cp_async16_ca(void* smem_ptr, const void* gptr) {
    uint32_t sa = (uint32_t)__cvta_generic_to_shared(smem_ptr);
    asm volatile("cp.async.ca.shared.global [%0], [%1], 16;\n" :: "r"(sa), "l"(gptr));
}
__device__ __forceinline__ void cp_commit() {
    asm volatile("cp.async.commit_group;\n");
}
__device__ __forceinline__ void cp_wait0() {
    asm volatile("cp.async.wait_group 0;\n" ::: "memory");
}
__device__ __forceinline__ void cp_wait3() {
    asm volatile("cp.async.wait_group 3;\n" ::: "memory");
}
__device__ __forceinline__ void cp_wait4() {
    asm volatile("cp.async.wait_group 4;\n" ::: "memory");
}
__device__ __forceinline__ void ldsm_x4(uint32_t& r0, uint32_t& r1,
                                        uint32_t& r2, uint32_t& r3, uint32_t a) {
    asm volatile("ldmatrix.sync.aligned.m8n8.x4.shared.b16 {%0,%1,%2,%3}, [%4];"
                 : "=r"(r0), "=r"(r1), "=r"(r2), "=r"(r3) : "r"(a));
}
__device__ __forceinline__ void ldsm_x4t(uint32_t& r0, uint32_t& r1,
                                         uint32_t& r2, uint32_t& r3, uint32_t a) {
    asm volatile("ldmatrix.sync.aligned.m8n8.x4.trans.shared.b16 {%0,%1,%2,%3}, [%4];"
                 : "=r"(r0), "=r"(r1), "=r"(r2), "=r"(r3) : "r"(a));
}
__device__ __forceinline__ void mma_f16(
    float& d0, float& d1, float& d2, float& d3,
    uint32_t a0, uint32_t a1, uint32_t a2, uint32_t a3,
    uint32_t b0, uint32_t b1)
{
    asm volatile(
        "mma.sync.aligned.m16n8k16.row.col.f32.f16.f16.f32 "
        "{%0,%1,%2,%3}, {%4,%5,%6,%7}, {%8,%9}, {%0,%1,%2,%3};\n"
        : "+f"(d0), "+f"(d1), "+f"(d2), "+f"(d3)
        : "r"(a0), "r"(a1), "r"(a2), "r"(a3), "r"(b0), "r"(b1));
}
// fp16-accumulate variant: 2x throughput of f32-acc on legacy HMMA
__device__ __forceinline__ void mma_f16h(
    uint32_t& c0, uint32_t& c1,
    uint32_t a0, uint32_t a1, uint32_t a2, uint32_t a3,
    uint32_t b0, uint32_t b1)
{
    asm volatile(
        "mma.sync.aligned.m16n8k16.row.col.f16.f16.f16.f16 "
        "{%0,%1}, {%2,%3,%4,%5}, {%6,%7}, {%0,%1};\n"
        : "+r"(c0), "+r"(c1)
        : "r"(a0), "r"(a1), "r"(a2), "r"(a3), "r"(b0), "r"(b1));
}

// ---------------------------------------------------------------------------
// f32 -> f16 (RN), 8 elems/thread
// ---------------------------------------------------------------------------
__global__ __launch_bounds__(256) void f2h(const float* __restrict__ s,
                                           uint16_t* __restrict__ d, int n8)
{
    int i = blockIdx.x*blockDim.x + threadIdx.x;
    if (i >= n8) return;
    float4 a = ((const float4*)s)[2*i];
    float4 b = ((const float4*)s)[2*i+1];
    __half2 h0 = __floats2half2_rn(a.x, a.y);
    __half2 h1 = __floats2half2_rn(a.z, a.w);
    __half2 h2 = __floats2half2_rn(b.x, b.y);
    __half2 h3 = __floats2half2_rn(b.z, b.w);
    uint4 o;
    o.x = *(uint32_t*)&h0; o.y = *(uint32_t*)&h1;
    o.z = *(uint32_t*)&h2; o.w = *(uint32_t*)&h3;
    ((uint4*)d)[i] = o;
}

__global__ __launch_bounds__(256) void w2h(KVWeights wts, uint16_t* __restrict__ d)
{
    const int widx = blockIdx.y;
    const float* s = wts.w[widx];
    uint16_t* dst = d + (size_t)widx*CAdim*CH;
    int i = blockIdx.x*blockDim.x + threadIdx.x;
    float4 a = ((const float4*)s)[2*i];
    float4 b = ((const float4*)s)[2*i+1];
    __half2 h0 = __floats2half2_rn(a.x, a.y);
    __half2 h1 = __floats2half2_rn(a.z, a.w);
    __half2 h2 = __floats2half2_rn(b.x, b.y);
    __half2 h3 = __floats2half2_rn(b.z, b.w);
    uint4 o;
    o.x = *(uint32_t*)&h0; o.y = *(uint32_t*)&h1;
    o.z = *(uint32_t*)&h2; o.w = *(uint32_t*)&h3;
    ((uint4*)dst)[i] = o;
}

// ---------------------------------------------------------------------------
// main fp16 GEMM, 4 warps, warp tile 64x64, 5-stage distance-4 pipeline.
// fp16 accumulation with fp32 promotion every 2 K-tiles (K=64 chunks).
// mode: 0 = f32 out, 1 = f32 out + residual + bias, 2 = f16 out (C16)
// ---------------------------------------------------------------------------
__global__ void __launch_bounds__(128, 2) gemm_f16(
    const __half* __restrict__ A, const __half* __restrict__ B,
    float* __restrict__ C, uint16_t* __restrict__ C16,
    const float* __restrict__ residual, const float* __restrict__ bias,
    int mode)
{
    extern __shared__ __align__(16) char smem[];
    const uint32_t sb = smem_u32(smem);
    const int m0 = blockIdx.y * BM;
    const int n0 = blockIdx.x * BN;
    const int tid  = threadIdx.x;
    const int lane = tid & 31;
    const int warp = tid >> 5;       // 0..3
    const int wm = warp >> 1;        // 0..1 -> 64 rows
    const int wn = warp & 1;         // 0..1 -> 64 cols
    const int gid  = lane >> 2;
    const int tid4 = lane & 3;

    float acc[4][8][4];              // master fp32 accumulator
    uint32_t acch[4][8][2];          // fp16 chunk accumulator (half2 pairs)
#pragma unroll
    for (int i = 0; i < 4; i++)
#pragma unroll
        for (int j = 0; j < 8; j++) {
#pragma unroll
            for (int t = 0; t < 4; t++) acc[i][j][t] = 0.0f;
            acch[i][j][0] = 0u; acch[i][j][1] = 0u;
        }

    auto issue = [&](int kt, int s) {
        char* base = smem + s*STAGE_BYTES;
        const int kk = kt * BKH;
#pragma unroll
        for (int i = 0; i < 4; i++) {
            int ch = tid + i*128;
            int r = ch >> 2, c = (ch & 3) * 8;
            cp_async16_ca(base + r*80 + c*2, A + (size_t)(m0 + r)*CH + kk + c);
        }
#pragma unroll
        for (int i = 0; i < 4; i++) {
            int ch = tid + i*128;
            int r = ch >> 4, c = (ch & 15) * 8;
            cp_async16(base + A_ST_BYTES + r*272 + c*2,
                       B + (size_t)(kk + r)*CH + n0 + c);
        }
    };

#pragma unroll
    for (int p = 0; p < 4; p++) { issue(p, p); cp_commit(); }

    const uint32_t aOfs = (uint32_t)(wm*64 + (lane & 15))*80 + ((lane >> 4) * 16);
    const uint32_t bOfs = A_ST_BYTES + (uint32_t)(lane & 15)*272
                        + (wn*64 + (lane >> 4)*8)*2;

    for (int kt = 0; kt < KTILES; kt++) {
        cp_wait3();
        __syncthreads();
        if (kt + 4 < KTILES) issue(kt + 4, (kt + 4) % GSTG);
        cp_commit();

        const uint32_t sbase = sb + (kt % GSTG)*STAGE_BYTES;
#pragma unroll
        for (int ks = 0; ks < 2; ks++) {
            uint32_t a[4][4];
#pragma unroll
            for (int mt = 0; mt < 4; mt++)
                ldsm_x4(a[mt][0], a[mt][1], a[mt][2], a[mt][3],
                        sbase + aOfs + mt*16*80 + ks*32);
            uint32_t bq[4][4];
#pragma unroll
            for (int np = 0; np < 4; np++)
                ldsm_x4t(bq[np][0], bq[np][1], bq[np][2], bq[np][3],
                         sbase + bOfs + ks*16*272 + np*32);
#pragma unroll
            for (int mt = 0; mt < 4; mt++)
#pragma unroll
                for (int np = 0; np < 4; np++) {
                    mma_f16h(acch[mt][2*np][0], acch[mt][2*np][1],
                             a[mt][0], a[mt][1], a[mt][2], a[mt][3],
                             bq[np][0], bq[np][1]);
                    mma_f16h(acch[mt][2*np+1][0], acch[mt][2*np+1][1],
                             a[mt][0], a[mt][1], a[mt][2], a[mt][3],
                             bq[np][2], bq[np][3]);
                }
        }
        // promote fp16 chunk accumulator into fp32 master every 2 K-tiles
        if ((kt & 1) == 1 || kt == KTILES - 1) {
#pragma unroll
            for (int mt = 0; mt < 4; mt++)
#pragma unroll
                for (int nt = 0; nt < 8; nt++) {
                    float2 lo = __half22float2(*(__half2*)&acch[mt][nt][0]);
                    float2 hi = __half22float2(*(__half2*)&acch[mt][nt][1]);
                    acc[mt][nt][0] += lo.x; acc[mt][nt][1] += lo.y;
                    acc[mt][nt][2] += hi.x; acc[mt][nt][3] += hi.y;
                    acch[mt][nt][0] = 0u;   acch[mt][nt][1] = 0u;
                }
        }
        __syncthreads();
    }

#pragma unroll
    for (int mt = 0; mt < 4; mt++) {
        int row0 = m0 + wm*64 + mt*16 + gid;
#pragma unroll
        for (int nt = 0; nt < 8; nt++) {
            int col = n0 + wn*64 + nt*8 + tid4*2;
            float2 v0 = make_float2(acc[mt][nt][0], acc[mt][nt][1]);
            float2 v1 = make_float2(acc[mt][nt][2], acc[mt][nt][3]);
            if (mode == 2) {
                __half2 h0 = __floats2half2_rn(v0.x, v0.y);
                __half2 h1 = __floats2half2_rn(v1.x, v1.y);
                *(uint32_t*)(C16 + (size_t)row0*CH + col)     = *(uint32_t*)&h0;
                *(uint32_t*)(C16 + (size_t)(row0+8)*CH + col) = *(uint32_t*)&h1;
            } else {
                if (mode == 1) {
                    float2 bi = *(const float2*)(bias + col);
                    float2 r0 = *(const float2*)(residual + (size_t)row0*CH + col);
                    float2 r1 = *(const float2*)(residual + (size_t)(row0+8)*CH + col);
                    v0.x += r0.x + bi.x; v0.y += r0.y + bi.y;
                    v1.x += r1.x + bi.x; v1.y += r1.y + bi.y;
                }
                *(float2*)(C + (size_t)row0*CH + col)     = v0;
                *(float2*)(C + (size_t)(row0+8)*CH + col) = v1;
            }
        }
    }
}

// ---------------------------------------------------------------------------
// KV projections, fp16 -> fp16 K/V outputs; 6-stage distance-5 pipeline
// ---------------------------------------------------------------------------
__global__ void __launch_bounds__(256, 2) kv_proj_f16(const uint16_t* __restrict__ ehsH,
                                                      const uint16_t* __restrict__ wkv)
{
    extern __shared__ __align__(16) char smem[];
    const uint32_t sb = smem_u32(smem);
    const int job = blockIdx.y;
    const int seg = c_job_seg[job];
    const int isv = (job >= 6);
    const int m0  = c_job_m0[job];
    const int st  = c_seg_start[seg];
    const int len = c_seg_len[seg];
    const int nrows = 2*len;
    const uint16_t* W = wkv + (size_t)(isv*4 + seg)*CAdim*CH;
    uint16_t* O = isv ? g_VH : g_KH;
    const int n0 = blockIdx.x * 64;
    const int tid = threadIdx.x;
    const int lane = tid & 31;
    const int warp = tid >> 5;
    const int wm = warp >> 1;
    const int wn = warp & 1;

    for (int i = tid; i < KV_STG*KV_E_B/4; i += 256) {
        int s = i / (KV_E_B/4), off = i % (KV_E_B/4);
        *(uint32_t*)(smem + s*KV_STAGE_B + off*4) = 0;
    }
    __syncthreads();

    auto issue = [&](int kt, int s) {
        char* base = smem + s*KV_STAGE_B;
        const int kk = kt * KV_KC;
#pragma unroll
        for (int i = 0; i < 2; i++) {
            int ch = tid + i*256;
            int r = ch >> 3, c = ch & 7;
            int m = m0 + r;
            if (m < nrows) {
                int b = m / len, l = st + m % len;
                cp_async16(base + r*KV_ROWB + c*16,
                           ehsH + ((size_t)(b*LTOT + l))*CAdim + kk + c*8);
            }
        }
#pragma unroll
        for (int i = 0; i < 2; i++) {
            int ch = tid + i*256;
            int r = ch >> 3, c = ch & 7;
            cp_async16(base + KV_E_B + r*KV_ROWB + c*16,
                       W + (size_t)(kk + r)*CH + n0 + c*8);
        }
    };

    float acc[4][4];
#pragma unroll
    for (int i = 0; i < 4; i++)
#pragma unroll
        for (int t = 0; t < 4; t++) acc[i][t] = 0.0f;

#pragma unroll
    for (int p = 0; p < 5; p++) { issue(p, p); cp_commit(); }

    const uint32_t aOfs = (uint32_t)(wm*16 + (lane & 15))*KV_ROWB + ((lane >> 4)*16);
    const uint32_t bOfs = KV_E_B + (uint32_t)(lane & 15)*KV_ROWB
                        + (wn*32 + (lane >> 4)*8)*2;

    for (int kt = 0; kt < KV_IT; kt++) {
        cp_wait4();
        __syncthreads();
        if (kt + 5 < KV_IT) issue(kt + 5, (kt + 5) % KV_STG);
        cp_commit();

        const uint32_t sbase = sb + (kt % KV_STG)*KV_STAGE_B;
#pragma unroll
        for (int ks = 0; ks < 4; ks++) {
            uint32_t a[4];
            ldsm_x4(a[0], a[1], a[2], a[3], sbase + aOfs + ks*32);
            uint32_t bq[2][4];
#pragma unroll
            for (int np = 0; np < 2; np++)
                ldsm_x4t(bq[np][0], bq[np][1], bq[np][2], bq[np][3],
                         sbase + bOfs + ks*16*KV_ROWB + np*32);
#pragma unroll
            for (int np = 0; np < 2; np++) {
                mma_f16(acc[2*np][0], acc[2*np][1], acc[2*np][2], acc[2*np][3],
                        a[0], a[1], a[2], a[3], bq[np][0], bq[np][1]);
                mma_f16(acc[2*np+1][0], acc[2*np+1][1], acc[2*np+1][2], acc[2*np+1][3],
                        a[0], a[1], a[2], a[3], bq[np][2], bq[np][3]);
            }
        }
        __syncthreads();
    }

    float* so = (float*)smem;
    const int gid = lane >> 2, tid4 = lane & 3;
#pragma unroll
    for (int nt = 0; nt < 4; nt++) {
        int r = wm*16 + gid;
        int cc = wn*32 + nt*8 + tid4*2;
        *(float2*)(so + r*68 + cc)     = make_float2(acc[nt][0], acc[nt][1]);
        *(float2*)(so + (r+8)*68 + cc) = make_float2(acc[nt][2], acc[nt][3]);
    }
    __syncthreads();
    for (int idx = tid; idx < 64*16; idx += 256) {
        int r = idx >> 4, c = (idx & 15) << 2;
        int m = m0 + r;
        if (m < nrows) {
            int b = m / len, l = st + m % len;
            float4 v = *(float4*)(so + r*68 + c);
            __half2 h0 = __floats2half2_rn(v.x, v.y);
            __half2 h1 = __floats2half2_rn(v.z, v.w);
            uint2 u; u.x = *(uint32_t*)&h0; u.y = *(uint32_t*)&h1;
            *(uint2*)(O + ((size_t)(b*LTOT + l))*CH + n0 + c) = u;
        }
    }
}

// ---------------------------------------------------------------------------
// Attention via tensor cores (unchanged)
// ---------------------------------------------------------------------------
__global__ __launch_bounds__(256) void attn_mma(
    const uint16_t* __restrict__ QH, const uint16_t* __restrict__ KH,
    const uint16_t* __restrict__ VH, uint16_t* __restrict__ OH)
{
    extern __shared__ __align__(16) char smem[];
    const uint32_t sb = smem_u32(smem);
    const int b = blockIdx.z, h = blockIdx.y;
    const int q0 = blockIdx.x * 128;
    const int tid = threadIdx.x;
    const int lane = tid & 31;
    const int w = tid >> 5;
    const int gid = lane >> 2, tid4 = lane & 3;

    for (int i = tid; i < 176; i += 256) {
        int arr = i / 88, rem = i % 88;
        int r = 101 + rem/8, c = rem & 7;
        *(uint4*)(smem + (arr ? AV_OFF : AK_OFF) + r*AT_ROWB + c*16) =
            make_uint4(0,0,0,0);
    }
    for (int i = tid; i < 1024; i += 256) {
        int r = i >> 3, c = i & 7;
        cp_async16(smem + AQ_OFF + r*AT_ROWB + c*16,
                   QH + ((size_t)(b*SEQ) + q0 + r)*CH + h*HDIM + c*8);
    }
    for (int i = tid; i < 808; i += 256) {
        int r = i >> 3, c = i & 7;
        cp_async16(smem + AK_OFF + r*AT_ROWB + c*16,
                   KH + ((size_t)(b*LTOT) + r)*CH + h*HDIM + c*8);
        cp_async16(smem + AV_OFF + r*AT_ROWB + c*16,
                   VH + ((size_t)(b*LTOT) + r)*CH + h*HDIM + c*8);
    }
    cp_commit();
    cp_wait0();
    __syncthreads();

    const uint32_t aQ = sb + AQ_OFF + (uint32_t)(w*16 + (lane & 15))*AT_ROWB
                      + ((lane >> 4)*16);
    const uint32_t aK = sb + AK_OFF + (uint32_t)(lane & 15)*AT_ROWB
                      + ((lane >> 4)*16);
    float sc[14][4];
#pragma unroll
    for (int t = 0; t < 14; t++)
#pragma unroll
        for (int j = 0; j < 4; j++) sc[t][j] = 0.0f;

#pragma unroll
    for (int ks = 0; ks < 4; ks++) {
        uint32_t qa[4];
        ldsm_x4(qa[0], qa[1], qa[2], qa[3], aQ + ks*32);
#pragma unroll
        for (int nt = 0; nt < 7; nt++) {
            uint32_t kb[4];
            ldsm_x4(kb[0], kb[1], kb[2], kb[3], aK + nt*16*AT_ROWB + ks*32);
            mma_f16(sc[2*nt][0], sc[2*nt][1], sc[2*nt][2], sc[2*nt][3],
                    qa[0], qa[1], qa[2], qa[3], kb[0], kb[2]);
            mma_f16(sc[2*nt+1][0], sc[2*nt+1][1], sc[2*nt+1][2], sc[2*nt+1][3],
                    qa[0], qa[1], qa[2], qa[3], kb[1], kb[3]);
        }
    }

    float sA0=0.f, sA1=0.f, sA2=0.f, sA3=0.f;
    float sB0=0.f, sB1=0.f, sB2=0.f, sB3=0.f;
#pragma unroll
    for (int t = 0; t < 14; t++) {
        const int c0 = t*8 + tid4*2, c1 = c0 + 1;
        float p0 = (c0 < 101) ? __expf(sc[t][0]*0.125f) : 0.f;
        float p1 = (c1 < 101) ? __expf(sc[t][1]*0.125f) : 0.f;
        float p2 = (c0 < 101) ? __expf(sc[t][2]*0.125f) : 0.f;
        float p3 = (c1 < 101) ? __expf(sc[t][3]*0.125f) : 0.f;
        sc[t][0] = p0; sc[t][1] = p1; sc[t][2] = p2; sc[t][3] = p3;
        if (c0 < 77) { sA0 += p0; sB0 += p2; }
        else if (c0 < 81) { sA1 += p0; sB1 += p2; }
        else if (c0 < 85) { sA2 += p0; sB2 += p2; }
        else { sA3 += p0; sB3 += p2; }
        if (c1 < 77) { sA0 += p1; sB0 += p3; }
        else if (c1 < 81) { sA1 += p1; sB1 += p3; }
        else if (c1 < 85) { sA2 += p1; sB2 += p3; }
        else { sA3 += p1; sB3 += p3; }
    }
#pragma unroll
    for (int d = 1; d <= 2; d <<= 1) {
        sA0 += __shfl_xor_sync(0xffffffffu, sA0, d);
        sA1 += __shfl_xor_sync(0xffffffffu, sA1, d);
        sA2 += __shfl_xor_sync(0xffffffffu, sA2, d);
        sA3 += __shfl_xor_sync(0xffffffffu, sA3, d);
        sB0 += __shfl_xor_sync(0xffffffffu, sB0, d);
        sB1 += __shfl_xor_sync(0xffffffffu, sB1, d);
        sB2 += __shfl_xor_sync(0xffffffffu, sB2, d);
        sB3 += __shfl_xor_sync(0xffffffffu, sB3, d);
    }
    const float iA0 = 1.f/sA0, iA1 = 1.f/sA1, iA2 = 1.f/sA2, iA3 = 1.f/sA3;
    const float iB0 = 1.f/sB0, iB1 = 1.f/sB1, iB2 = 1.f/sB2, iB3 = 1.f/sB3;

    auto nrmA = [&](int c, float p) {
        return p * (c < 77 ? iA0 : c < 81 ? iA1 : c < 85 ? iA2 : iA3);
    };
    auto nrmB = [&](int c, float p) {
        return p * (c < 77 ? iB0 : c < 81 ? iB1 : c < 85 ? iB2 : iB3);
    };

    const uint32_t aV = sb + AV_OFF + (uint32_t)(lane & 15)*AT_ROWB
                      + ((lane >> 4)*8)*2;
    float oa[8][4];
#pragma unroll
    for (int i = 0; i < 8; i++)
#pragma unroll
        for (int j = 0; j < 4; j++) oa[i][j] = 0.0f;

#pragma unroll
    for (int kp = 0; kp < 7; kp++) {
        const int t0 = 2*kp, t1 = 2*kp + 1;
        const int c0 = t0*8 + tid4*2, c1 = c0 + 1;
        const int d0 = t1*8 + tid4*2, d1 = d0 + 1;
        __half2 h0 = __floats2half2_rn(nrmA(c0, sc[t0][0]), nrmA(c1, sc[t0][1]));
        __half2 h1 = __floats2half2_rn(nrmB(c0, sc[t0][2]), nrmB(c1, sc[t0][3]));
        __half2 h2 = __floats2half2_rn(nrmA(d0, sc[t1][0]), nrmA(d1, sc[t1][1]));
        __half2 h3 = __floats2half2_rn(nrmB(d0, sc[t1][2]), nrmB(d1, sc[t1][3]));
        uint32_t pa0 = *(uint32_t*)&h0, pa1 = *(uint32_t*)&h1;
        uint32_t pa2 = *(uint32_t*)&h2, pa3 = *(uint32_t*)&h3;
#pragma unroll
        for (int nv = 0; nv < 4; nv++) {
            uint32_t vb[4];
            ldsm_x4t(vb[0], vb[1], vb[2], vb[3],
                     aV + kp*16*AT_ROWB + nv*32);
            mma_f16(oa[2*nv][0], oa[2*nv][1], oa[2*nv][2], oa[2*nv][3],
                    pa0, pa1, pa2, pa3, vb[0], vb[1]);
            mma_f16(oa[2*nv+1][0], oa[2*nv+1][1], oa[2*nv+1][2], oa[2*nv+1][3],
                    pa0, pa1, pa2, pa3, vb[2], vb[3]);
        }
    }

    const int mrow = q0 + w*16 + gid;
    uint16_t* ob0 = OH + ((size_t)b*SEQ + mrow)*CH + h*HDIM;
    uint16_t* ob1 = ob0 + (size_t)8*CH;
#pragma unroll
    for (int t = 0; t < 8; t++) {
        int cc = t*8 + tid4*2;
        __half2 u0 = __floats2half2_rn(oa[t][0], oa[t][1]);
        __half2 u1 = __floats2half2_rn(oa[t][2], oa[t][3]);
        *(uint32_t*)(ob0 + cc) = *(uint32_t*)&u0;
        *(uint32_t*)(ob1 + cc) = *(uint32_t*)&u1;
    }
}

// ---------------------------------------------------------------------------
extern "C" void kernel_launch(void* const* d_in, const int* in_sizes, int n_in,
                              void* d_out, int out_size)
{
    const float* hs   = (const float*)d_in[0];
    const float* ehs  = (const float*)d_in[1];
    const float* wq   = (const float*)d_in[2];
    const float* wout = (const float*)d_in[11];
    const float* bout = (const float*)d_in[12];
    float* out = (float*)d_out;

    KVWeights wts;
    wts.w[0] = (const float*)d_in[3];
    wts.w[1] = (const float*)d_in[5];
    wts.w[2] = (const float*)d_in[7];
    wts.w[3] = (const float*)d_in[9];
    wts.w[4] = (const float*)d_in[4];
    wts.w[5] = (const float*)d_in[6];
    wts.w[6] = (const float*)d_in[8];
    wts.w[7] = (const float*)d_in[10];

    uint16_t *pQH, *pKH, *pVH, *pHsH, *pAttH, *pWqH, *pWoH, *pWkvH, *pEhsH;
    cudaGetSymbolAddress((void**)&pQH,   g_QH);
    cudaGetSymbolAddress((void**)&pKH,   g_KH);
    cudaGetSymbolAddress((void**)&pVH,   g_VH);
    cudaGetSymbolAddress((void**)&pHsH,  g_hsH);
    cudaGetSymbolAddress((void**)&pAttH, g_AttH);
    cudaGetSymbolAddress((void**)&pWqH,  g_WqH);
    cudaGetSymbolAddress((void**)&pWoH,  g_WoH);
    cudaGetSymbolAddress((void**)&pWkvH, g_WkvH);
    cudaGetSymbolAddress((void**)&pEhsH, g_ehsH);

    cudaFuncSetAttribute(gemm_f16,
                         cudaFuncAttributeMaxDynamicSharedMemorySize, GEMM_SMEM);
    cudaFuncSetAttribute(kv_proj_f16,
                         cudaFuncAttributeMaxDynamicSharedMemorySize, KV_SMEM);
    cudaFuncSetAttribute(attn_mma,
                         cudaFuncAttributeMaxDynamicSharedMemorySize, AT_SMEM);

    const int M = NUM_B*SEQ;   // 8192

    const int nhs8 = M*CH/8;
    const int nw8  = CH*CH/8;
    const int nehs8 = NUM_B*LTOT*CAdim/8;

    // ---- fork: side stream runs the KV branch ----
    cudaEventRecord(g_evFork, 0);
    cudaStreamWaitEvent(g_s2, g_evFork, 0);

    w2h<<<dim3(CAdim*CH/8/256, 8), 256, 0, g_s2>>>(wts, pWkvH);
    f2h<<<(nehs8 + 255)/256, 256, 0, g_s2>>>(ehs, pEhsH, nehs8);
    kv_proj_f16<<<dim3(CH/64, 12), 256, KV_SMEM, g_s2>>>(pEhsH, pWkvH);
    cudaEventRecord(g_evJoin, g_s2);

    // ---- main stream: Q branch ----
    f2h<<<(nhs8 + 255)/256, 256>>>(hs, pHsH, nhs8);
    f2h<<<(nw8 + 255)/256, 256>>>(wq, pWqH, nw8);
    gemm_f16<<<dim3(CH/BN, M/BM), 128, GEMM_SMEM>>>(
        (const __half*)pHsH, (const __half*)pWqH,
        nullptr, pQH, nullptr, nullptr, 2);
    f2h<<<(nw8 + 255)/256, 256>>>(wout, pWoH, nw8);

    // ---- join, then attention + output projection ----
    cudaStreamWaitEvent(0, g_evJoin, 0);
    attn_mma<<<dim3(SEQ/128, NHEADS, NUM_B), 256, AT_SMEM>>>(
        pQH, pKH, pVH, pAttH);
    gemm_f16<<<dim3(CH/BN, M/BM), 128, GEMM_SMEM>>>(
        (const __half*)pAttH, (const __half*)pWoH,
        out, nullptr, hs, bout, 1);
}